// round 1
// baseline (speedup 1.0000x reference)
#include <cuda_runtime.h>

#define BB   4
#define NN   2048
#define H    768
#define NH   12
#define HD   64
#define DEG  16
#define NREL 64
#define EDG  (BB*NN*DEG)    // 131072
#define ROWS (BB*NN)        // 8192

// Scratch for Q, K, V projections: 3 * 8192 * 768 floats = 75.5 MB
__device__ float g_QKV[3ull * ROWS * H];

// ---------------------------------------------------------------------------
// Fused QKV projection: C = X @ W^T + b for W in {Wq, Wk, Wv}
// X: (8192, 768) row-major, W: (768, 768) row-major (Linear weight), K-contig.
// Tile: BM=128, BN=64, BK=16, 256 threads, 8x4 per-thread microtile.
// Grid: (36, 64) -> bx/12 selects matrix, (bx%12)*64 = col block, by*128 = row.
// ---------------------------------------------------------------------------
#define BM 128
#define BN 64
#define BK 16

__global__ __launch_bounds__(256) void qkv_gemm(
    const float* __restrict__ X,
    const float* __restrict__ Wq, const float* __restrict__ bq,
    const float* __restrict__ Wk, const float* __restrict__ bk,
    const float* __restrict__ Wv, const float* __restrict__ bv)
{
    __shared__ float Xs[BK][BM + 4];
    __shared__ float Ws[BK][BN + 4];

    const int bx = blockIdx.x;            // 0..35
    const int by = blockIdx.y;            // 0..63
    const int mat = bx / 12;              // 0=Q, 1=K, 2=V
    const int n0 = (bx % 12) * BN;
    const int m0 = by * BM;

    const float* W    = (mat == 0) ? Wq : (mat == 1) ? Wk : Wv;
    const float* bias = (mat == 0) ? bq : (mat == 1) ? bk : bv;
    float* C = g_QKV + (size_t)mat * ROWS * H;

    const int tid = threadIdx.x;
    const int tx = tid & 15;              // 0..15 -> N
    const int ty = tid >> 4;              // 0..15 -> M

    float acc[8][4];
    #pragma unroll
    for (int i = 0; i < 8; i++)
        #pragma unroll
        for (int j = 0; j < 4; j++) acc[i][j] = 0.f;

    for (int k0 = 0; k0 < H; k0 += BK) {
        // Load X tile (128x16) transposed into Xs[k][m]
        #pragma unroll
        for (int s = 0; s < 2; s++) {
            int slot = tid + s * 256;         // 0..511 float4 slots
            int r  = slot >> 2;               // 0..127
            int kq = slot & 3;                // which float4 along K
            float4 v = *(const float4*)(X + (size_t)(m0 + r) * H + k0 + kq * 4);
            Xs[kq * 4 + 0][r] = v.x;
            Xs[kq * 4 + 1][r] = v.y;
            Xs[kq * 4 + 2][r] = v.z;
            Xs[kq * 4 + 3][r] = v.w;
        }
        {
            int slot = tid;                   // 0..255 float4 slots
            int n  = slot >> 2;               // 0..63
            int kq = slot & 3;
            float4 v = *(const float4*)(W + (size_t)(n0 + n) * H + k0 + kq * 4);
            Ws[kq * 4 + 0][n] = v.x;
            Ws[kq * 4 + 1][n] = v.y;
            Ws[kq * 4 + 2][n] = v.z;
            Ws[kq * 4 + 3][n] = v.w;
        }
        __syncthreads();

        #pragma unroll
        for (int k = 0; k < BK; k++) {
            float a[8], b[4];
            #pragma unroll
            for (int i = 0; i < 8; i++) a[i] = Xs[k][ty * 8 + i];
            #pragma unroll
            for (int j = 0; j < 4; j++) b[j] = Ws[k][tx * 4 + j];
            #pragma unroll
            for (int i = 0; i < 8; i++)
                #pragma unroll
                for (int j = 0; j < 4; j++)
                    acc[i][j] += a[i] * b[j];
        }
        __syncthreads();
    }

    // Epilogue: add bias, coalesced float4 stores
    float4 bv4;
    bv4.x = bias[n0 + tx * 4 + 0];
    bv4.y = bias[n0 + tx * 4 + 1];
    bv4.z = bias[n0 + tx * 4 + 2];
    bv4.w = bias[n0 + tx * 4 + 3];
    #pragma unroll
    for (int i = 0; i < 8; i++) {
        int row = m0 + ty * 8 + i;
        float4 o;
        o.x = acc[i][0] + bv4.x;
        o.y = acc[i][1] + bv4.y;
        o.z = acc[i][2] + bv4.z;
        o.w = acc[i][3] + bv4.w;
        *(float4*)(C + (size_t)row * H + n0 + tx * 4) = o;
    }
}

// ---------------------------------------------------------------------------
// Edge attention. Edge list is structured: segment (b,dst) = contiguous block
// of DEG=16 edges at e0 = seg*16. One block per node (8192 blocks), 192 thr.
//   phase 1: stage Q row in smem (reused 16x); read src/rel indices
//   phase 2: logits[h][d] = Q_h . (K[src_d]_h + Ek[rel_d]_h) / 8
//            thread map h=tid/16, d=tid%16 -> Qs reads broadcast per 16 lanes
//   phase 3: 16-way softmax per head (12 threads)
//   phase 4: out[c] = sum_d attn[h(c)][d] * (V[src_d][c] + Ev[rel_d][c])
//            thread tid owns float4 column tid -> fully coalesced V reads
// ---------------------------------------------------------------------------
__global__ __launch_bounds__(192) void attn_kernel(
    const int* __restrict__ ei,
    const float* __restrict__ Ek, const float* __restrict__ Ev,
    float* __restrict__ out)
{
    const float* Q = g_QKV;
    const float* K = g_QKV + (size_t)ROWS * H;
    const float* V = g_QKV + 2ull * ROWS * H;

    __shared__ float Qs[H];
    __shared__ int   srcs[DEG], rels[DEG];
    __shared__ float logits[NH][DEG];
    __shared__ float attn[NH][DEG];
    __shared__ int   sb, sdst;

    const int seg = blockIdx.x;
    const int tid = threadIdx.x;
    const int e0 = seg * DEG;

    if (tid < DEG) {
        srcs[tid] = ei[2 * EDG + e0 + tid];
        rels[tid] = ei[3 * EDG + e0 + tid];
    }
    if (tid == 0) { sb = ei[e0]; sdst = ei[EDG + e0]; }
    __syncthreads();

    const int brow = sb * NN;
    const int qrow = brow + sdst;

    // stage Q row: 192 threads x 1 float4 = 768 floats
    *(float4*)(Qs + tid * 4) = *(const float4*)(Q + (size_t)qrow * H + tid * 4);
    __syncthreads();

    // phase 2: logits
    {
        const int h = tid >> 4;   // 0..11
        const int d = tid & 15;   // 0..15
        const float* kp = K  + (size_t)(brow + srcs[d]) * H + h * HD;
        const float* ep = Ek + (size_t)rels[d] * H + h * HD;
        const float* qp = Qs + h * HD;
        float acc = 0.f;
        #pragma unroll
        for (int j = 0; j < HD / 4; j++) {
            float4 kv = *(const float4*)(kp + j * 4);
            float4 ev = *(const float4*)(ep + j * 4);
            float4 qv = *(const float4*)(qp + j * 4);
            acc += qv.x * (kv.x + ev.x) + qv.y * (kv.y + ev.y)
                 + qv.z * (kv.z + ev.z) + qv.w * (kv.w + ev.w);
        }
        logits[h][d] = acc * 0.125f;   // / sqrt(64)
    }
    __syncthreads();

    // phase 3: softmax over the 16 neighbors, per head
    if (tid < NH) {
        float m = -1e30f;
        #pragma unroll
        for (int d = 0; d < DEG; d++) m = fmaxf(m, logits[tid][d]);
        float ex[DEG];
        float s = 0.f;
        #pragma unroll
        for (int d = 0; d < DEG; d++) { ex[d] = __expf(logits[tid][d] - m); s += ex[d]; }
        float inv = 1.f / s;
        #pragma unroll
        for (int d = 0; d < DEG; d++) attn[tid][d] = ex[d] * inv;
    }
    __syncthreads();

    // phase 4: weighted sum of (V + Ev) over neighbors
    {
        const int h = tid >> 4;   // head of columns tid*4..tid*4+3
        float4 o = make_float4(0.f, 0.f, 0.f, 0.f);
        #pragma unroll
        for (int d = 0; d < DEG; d++) {
            const float a = attn[h][d];
            float4 vv = *(const float4*)(V  + (size_t)(brow + srcs[d]) * H + tid * 4);
            float4 ev = *(const float4*)(Ev + (size_t)rels[d] * H + tid * 4);
            o.x += a * (vv.x + ev.x);
            o.y += a * (vv.y + ev.y);
            o.z += a * (vv.z + ev.z);
            o.w += a * (vv.w + ev.w);
        }
        *(float4*)(out + (size_t)qrow * H + tid * 4) = o;
    }
}

extern "C" void kernel_launch(void* const* d_in, const int* in_sizes, int n_in,
                              void* d_out, int out_size)
{
    const float* X  = (const float*)d_in[0];
    const int*   ei = (const int*)  d_in[1];
    const float* Wq = (const float*)d_in[2];
    const float* bq = (const float*)d_in[3];
    const float* Wk = (const float*)d_in[4];
    const float* bk = (const float*)d_in[5];
    const float* Wv = (const float*)d_in[6];
    const float* bv = (const float*)d_in[7];
    const float* Ek = (const float*)d_in[8];
    const float* Ev = (const float*)d_in[9];
    float* out = (float*)d_out;

    dim3 grid(36, 64);
    qkv_gemm<<<grid, 256>>>(X, Wq, bq, Wk, bk, Wv, bv);
    attn_kernel<<<ROWS, 192>>>(ei, Ek, Ev, out);
}

// round 4
// speedup vs baseline: 2.5582x; 2.5582x over previous
#include <cuda_runtime.h>
#include <cuda_bf16.h>
#include <cstdint>

#define BB   4
#define NN   2048
#define H    768
#define NH   12
#define HD   64
#define DEG  16
#define NREL 64
#define EDG  (BB*NN*DEG)    // 131072
#define ROWS (BB*NN)        // 8192

// fp32 Q,K,V scratch (75.5 MB)
__device__ float g_QKV[3ull * ROWS * H];
// bf16 hi/lo splits of X and W
__device__ __nv_bfloat16 g_Xhi[(size_t)ROWS * H];
__device__ __nv_bfloat16 g_Xlo[(size_t)ROWS * H];
__device__ __nv_bfloat16 g_Whi[3ull * H * H];
__device__ __nv_bfloat16 g_Wlo[3ull * H * H];

// ===========================================================================
// helpers
// ===========================================================================
__device__ __forceinline__ uint32_t smem_u32(const void* p) {
    uint32_t a;
    asm("{ .reg .u64 t; cvta.to.shared.u64 t, %1; cvt.u32.u64 %0, t; }" : "=r"(a) : "l"(p));
    return a;
}
__device__ __forceinline__ void cp16(uint32_t dst, const void* src) {
    asm volatile("cp.async.cg.shared.global [%0], [%1], 16;" :: "r"(dst), "l"(src) : "memory");
}
__device__ __forceinline__ void cp_commit() {
    asm volatile("cp.async.commit_group;" ::: "memory");
}
template <int N>
__device__ __forceinline__ void cp_wait() {
    asm volatile("cp.async.wait_group %0;" :: "n"(N) : "memory");
}
__device__ __forceinline__ void ldm_x4(uint32_t* r, uint32_t addr) {
    asm volatile("ldmatrix.sync.aligned.m8n8.x4.shared.b16 {%0,%1,%2,%3}, [%4];"
                 : "=r"(r[0]), "=r"(r[1]), "=r"(r[2]), "=r"(r[3]) : "r"(addr));
}
__device__ __forceinline__ void mma_bf16(float* d, const uint32_t* a, uint32_t b0, uint32_t b1) {
    asm volatile(
        "mma.sync.aligned.m16n8k16.row.col.f32.bf16.bf16.f32 "
        "{%0,%1,%2,%3}, {%4,%5,%6,%7}, {%8,%9}, {%0,%1,%2,%3};"
        : "+f"(d[0]), "+f"(d[1]), "+f"(d[2]), "+f"(d[3])
        : "r"(a[0]), "r"(a[1]), "r"(a[2]), "r"(a[3]), "r"(b0), "r"(b1));
}

// ===========================================================================
// Kernel 0: fp32 -> (hi, lo) bf16 split for X and the three weight matrices
// ===========================================================================
__global__ void __launch_bounds__(256) convert_split(
    const float* __restrict__ X,
    const float* __restrict__ Wq, const float* __restrict__ Wk,
    const float* __restrict__ Wv)
{
    const size_t NX = (size_t)ROWS * H / 4;   // float4 count for X
    const size_t NW = (size_t)H * H / 4;      // per weight matrix
    const size_t TOT = NX + 3 * NW;
    for (size_t i = (size_t)blockIdx.x * blockDim.x + threadIdx.x; i < TOT;
         i += (size_t)gridDim.x * blockDim.x) {
        const float* src;
        __nv_bfloat16 *dh, *dl;
        size_t j;
        if (i < NX) { src = X; dh = g_Xhi; dl = g_Xlo; j = i; }
        else {
            size_t r = i - NX;
            int m = (int)(r / NW); j = r % NW;
            src = (m == 0) ? Wq : (m == 1) ? Wk : Wv;
            dh = g_Whi + (size_t)m * H * H;
            dl = g_Wlo + (size_t)m * H * H;
        }
        float4 v = ((const float4*)src)[j];
        __nv_bfloat16 h[4], l[4];
        h[0] = __float2bfloat16_rn(v.x); l[0] = __float2bfloat16_rn(v.x - __bfloat162float(h[0]));
        h[1] = __float2bfloat16_rn(v.y); l[1] = __float2bfloat16_rn(v.y - __bfloat162float(h[1]));
        h[2] = __float2bfloat16_rn(v.z); l[2] = __float2bfloat16_rn(v.z - __bfloat162float(h[2]));
        h[3] = __float2bfloat16_rn(v.w); l[3] = __float2bfloat16_rn(v.w - __bfloat162float(h[3]));
        ((ushort4*)dh)[j] = make_ushort4(*(unsigned short*)&h[0], *(unsigned short*)&h[1],
                                         *(unsigned short*)&h[2], *(unsigned short*)&h[3]);
        ((ushort4*)dl)[j] = make_ushort4(*(unsigned short*)&l[0], *(unsigned short*)&l[1],
                                         *(unsigned short*)&l[2], *(unsigned short*)&l[3]);
    }
}

// ===========================================================================
// Kernel 1: QKV GEMM via mma.sync bf16 3-pass. C = X @ W^T + b.
// Tile 128x128, BK=64. 8 warps: warp_m = wid&3 (32 rows), warp_n = wid>>2 (64 cols).
// Smem tile: 128 rows x 128B (64 bf16), 16B chunks XOR-swizzled: c ^= (row&7).
// Double-buffered cp.async pipeline. 12 k-iters.
// ===========================================================================
#define GBK 64
#define NKIT (H / GBK)          // 12
#define TILE_B 16384            // one tile: 128*128 bytes
#define BUF_B  (4 * TILE_B)     // Ahi, Alo, Bhi, Blo
#define GSM_TOTAL (2 * BUF_B)   // 131072

__device__ __forceinline__ uint32_t tile_off(int row, int c) {
    return (uint32_t)(row * 128 + ((c ^ (row & 7)) << 4));
}

__device__ __forceinline__ void load_tile_async(uint32_t dstbase,
                                                const __nv_bfloat16* __restrict__ g,
                                                int k0, int tid) {
    #pragma unroll
    for (int i = 0; i < 4; i++) {
        int chunk = tid + i * 256;          // 0..1023
        int row = chunk >> 3;
        int c = chunk & 7;
        cp16(dstbase + tile_off(row, c), g + (size_t)row * H + k0 + c * 8);
    }
}

__global__ void __launch_bounds__(256, 1) qkv_gemm_mma(
    const float* __restrict__ bq, const float* __restrict__ bk,
    const float* __restrict__ bv)
{
    extern __shared__ char sm[];
    const uint32_t sbase = smem_u32(sm);

    const int tid = threadIdx.x;
    const int bx = blockIdx.x;              // 0..1151
    const int mat = bx / 384;
    const int rem = bx % 384;
    const int nt = rem / 64, mt = rem % 64;
    const int m0 = mt * 128, n0 = nt * 128;

    const __nv_bfloat16* Agh = g_Xhi + (size_t)m0 * H;
    const __nv_bfloat16* Agl = g_Xlo + (size_t)m0 * H;
    const __nv_bfloat16* Bgh = g_Whi + (size_t)mat * H * H + (size_t)n0 * H;
    const __nv_bfloat16* Bgl = g_Wlo + (size_t)mat * H * H + (size_t)n0 * H;
    const float* bias = (mat == 0) ? bq : (mat == 1) ? bk : bv;
    float* C = g_QKV + (size_t)mat * ROWS * H;

    const int wid = tid >> 5, lane = tid & 31;
    const int warp_m = wid & 3;             // *32 rows
    const int warp_n = wid >> 2;            // *64 cols
    const int lrow = lane & 15, lch = lane >> 4;

    float acc[2][8][4];
    #pragma unroll
    for (int a = 0; a < 2; a++)
        #pragma unroll
        for (int b = 0; b < 8; b++)
            #pragma unroll
            for (int c = 0; c < 4; c++) acc[a][b][c] = 0.f;

    // prologue: prefetch iter 0 into buf 0
    load_tile_async(sbase + 0 * TILE_B, Agh, 0, tid);
    load_tile_async(sbase + 1 * TILE_B, Agl, 0, tid);
    load_tile_async(sbase + 2 * TILE_B, Bgh, 0, tid);
    load_tile_async(sbase + 3 * TILE_B, Bgl, 0, tid);
    cp_commit();

    for (int it = 0; it < NKIT; it++) {
        if (it + 1 < NKIT) {
            uint32_t nb = sbase + ((it + 1) & 1) * BUF_B;
            int k0 = (it + 1) * GBK;
            load_tile_async(nb + 0 * TILE_B, Agh, k0, tid);
            load_tile_async(nb + 1 * TILE_B, Agl, k0, tid);
            load_tile_async(nb + 2 * TILE_B, Bgh, k0, tid);
            load_tile_async(nb + 3 * TILE_B, Bgl, k0, tid);
            cp_commit();
            cp_wait<1>();
        } else {
            cp_wait<0>();
        }
        __syncthreads();

        const uint32_t buf = sbase + (it & 1) * BUF_B;
        const uint32_t sAh = buf, sAl = buf + TILE_B;
        const uint32_t sBh = buf + 2 * TILE_B, sBl = buf + 3 * TILE_B;

        #pragma unroll
        for (int kf = 0; kf < 4; kf++) {
            const int ch = kf * 2 + lch;
            uint32_t ah[2][4], al[2][4];
            #pragma unroll
            for (int mf = 0; mf < 2; mf++) {
                int r = warp_m * 32 + mf * 16 + lrow;
                uint32_t off = tile_off(r, ch);
                ldm_x4(ah[mf], sAh + off);
                ldm_x4(al[mf], sAl + off);
            }
            uint32_t bh[4][4], bl[4][4];
            #pragma unroll
            for (int ng = 0; ng < 4; ng++) {
                int r = warp_n * 64 + ng * 16 + lrow;
                uint32_t off = tile_off(r, ch);
                ldm_x4(bh[ng], sBh + off);
                ldm_x4(bl[ng], sBl + off);
            }
            #pragma unroll
            for (int mf = 0; mf < 2; mf++) {
                #pragma unroll
                for (int ng = 0; ng < 4; ng++) {
                    // nsub0: regs {0,2}; nsub1: regs {1,3}
                    float* a0 = acc[mf][ng * 2 + 0];
                    float* a1 = acc[mf][ng * 2 + 1];
                    mma_bf16(a0, ah[mf], bh[ng][0], bh[ng][2]);
                    mma_bf16(a0, ah[mf], bl[ng][0], bl[ng][2]);
                    mma_bf16(a0, al[mf], bh[ng][0], bh[ng][2]);
                    mma_bf16(a1, ah[mf], bh[ng][1], bh[ng][3]);
                    mma_bf16(a1, ah[mf], bl[ng][1], bl[ng][3]);
                    mma_bf16(a1, al[mf], bh[ng][1], bh[ng][3]);
                }
            }
        }
        __syncthreads();
    }

    // epilogue
    const int tr = lane >> 2, tc = (lane & 3) * 2;
    #pragma unroll
    for (int nf = 0; nf < 8; nf++) {
        const int col = n0 + warp_n * 64 + nf * 8 + tc;
        const float b0 = __ldg(bias + col), b1 = __ldg(bias + col + 1);
        #pragma unroll
        for (int mf = 0; mf < 2; mf++) {
            const int row = m0 + warp_m * 32 + mf * 16 + tr;
            float2 o0 = make_float2(acc[mf][nf][0] + b0, acc[mf][nf][1] + b1);
            float2 o1 = make_float2(acc[mf][nf][2] + b0, acc[mf][nf][3] + b1);
            *(float2*)(C + (size_t)row * H + col) = o0;
            *(float2*)(C + (size_t)(row + 8) * H + col) = o1;
        }
    }
}

// ===========================================================================
// Edge attention, 256 threads / node. Coalesced K/Ek row reads + 16-lane
// shfl reduction (phase 2); coalesced V accumulation (phase 4).
// ===========================================================================
__global__ void __launch_bounds__(256) attn_kernel(
    const int* __restrict__ ei,
    const float* __restrict__ Ek, const float* __restrict__ Ev,
    float* __restrict__ out)
{
    const float* Q = g_QKV;
    const float* K = g_QKV + (size_t)ROWS * H;
    const float* V = g_QKV + 2ull * ROWS * H;

    __shared__ float Qs[H];
    __shared__ int   srcs[DEG], rels[DEG];
    __shared__ float logits[NH][DEG];
    __shared__ float attn[NH][DEG];
    __shared__ int   sb, sdst;

    const int seg = blockIdx.x;
    const int tid = threadIdx.x;
    const int e0 = seg * DEG;

    if (tid < DEG) {
        srcs[tid] = ei[2 * EDG + e0 + tid];
        rels[tid] = ei[3 * EDG + e0 + tid];
    }
    if (tid == 0) { sb = ei[e0]; sdst = ei[EDG + e0]; }
    __syncthreads();

    const int brow = sb * NN;
    const int qrow = brow + sdst;

    if (tid < 192)
        *(float4*)(Qs + tid * 4) = *(const float4*)(Q + (size_t)qrow * H + tid * 4);
    __syncthreads();

    // phase 2: logits, coalesced row reads + shfl reduction
    {
        const int warp = tid >> 5, lane = tid & 31;
        const int hb = lane >> 4;
        const float4* qp = (const float4*)Qs;
        #pragma unroll
        for (int i = 0; i < 2; i++) {
            const int d = warp * 2 + i;
            const float4* kp = (const float4*)(K + (size_t)(brow + srcs[d]) * H);
            const float4* ep = (const float4*)(Ek + (size_t)rels[d] * H);
            float pp[6];
            #pragma unroll
            for (int j = 0; j < 6; j++) {
                int c4 = j * 32 + lane;
                float4 kv = kp[c4], ev = ep[c4], qv = qp[c4];
                pp[j] = qv.x * (kv.x + ev.x) + qv.y * (kv.y + ev.y)
                      + qv.z * (kv.z + ev.z) + qv.w * (kv.w + ev.w);
            }
            #pragma unroll
            for (int m = 8; m; m >>= 1)
                #pragma unroll
                for (int j = 0; j < 6; j++)
                    pp[j] += __shfl_xor_sync(0xffffffffu, pp[j], m);
            if ((lane & 15) == 0) {
                #pragma unroll
                for (int j = 0; j < 6; j++)
                    logits[j * 2 + hb][d] = pp[j] * 0.125f;
            }
        }
    }
    __syncthreads();

    // phase 3: 16-way softmax per head
    if (tid < NH) {
        float m = -1e30f;
        #pragma unroll
        for (int d = 0; d < DEG; d++) m = fmaxf(m, logits[tid][d]);
        float ex[DEG];
        float s = 0.f;
        #pragma unroll
        for (int d = 0; d < DEG; d++) { ex[d] = __expf(logits[tid][d] - m); s += ex[d]; }
        float inv = 1.f / s;
        #pragma unroll
        for (int d = 0; d < DEG; d++) attn[tid][d] = ex[d] * inv;
    }
    __syncthreads();

    // phase 4: weighted sum of (V + Ev), coalesced
    if (tid < 192) {
        const int h = tid >> 4;
        float4 o = make_float4(0.f, 0.f, 0.f, 0.f);
        #pragma unroll
        for (int d = 0; d < DEG; d++) {
            const float a = attn[h][d];
            float4 vv = *(const float4*)(V  + (size_t)(brow + srcs[d]) * H + tid * 4);
            float4 ev = *(const float4*)(Ev + (size_t)rels[d] * H + tid * 4);
            o.x += a * (vv.x + ev.x);
            o.y += a * (vv.y + ev.y);
            o.z += a * (vv.z + ev.z);
            o.w += a * (vv.w + ev.w);
        }
        *(float4*)(out + (size_t)qrow * H + tid * 4) = o;
    }
}

extern "C" void kernel_launch(void* const* d_in, const int* in_sizes, int n_in,
                              void* d_out, int out_size)
{
    const float* X  = (const float*)d_in[0];
    const int*   ei = (const int*)  d_in[1];
    const float* Wq = (const float*)d_in[2];
    const float* bq = (const float*)d_in[3];
    const float* Wk = (const float*)d_in[4];
    const float* bk = (const float*)d_in[5];
    const float* Wv = (const float*)d_in[6];
    const float* bv = (const float*)d_in[7];
    const float* Ek = (const float*)d_in[8];
    const float* Ev = (const float*)d_in[9];
    float* out = (float*)d_out;

    convert_split<<<2048, 256>>>(X, Wq, Wk, Wv);
    cudaFuncSetAttribute(qkv_gemm_mma, cudaFuncAttributeMaxDynamicSharedMemorySize, GSM_TOTAL);
    qkv_gemm_mma<<<1152, 256, GSM_TOTAL>>>(bq, bk, bv);
    attn_kernel<<<ROWS, 256>>>(ei, Ek, Ev, out);
}